// round 16
// baseline (speedup 1.0000x reference)
#include <cuda_runtime.h>
#include <cstdint>

#define N_NODES 10000
#define N_EDGES 320000

// ---------------- scratch (device globals; allocation-free) ----------------
__device__ float g_h[N_NODES * 64];                 // 2.56 MB
__device__ float g_agg[(size_t)N_NODES * 576];      // 23 MB; zeroed by k_fill_plus each call
__device__ int   g_count[N_NODES];                  // zeroed by k_scan after read
__device__ int   g_rowstart[N_NODES + 1];
__device__ int   g_cursor[N_NODES];
__device__ int   g_csr[N_EDGES];
__device__ int   g_send[N_EDGES];
__device__ int   g_recv[N_EDGES];
__device__ uint4 g_wfrag[4224];                     // fragment-ordered fp16 weights (67.6KB)

// uint4 offsets into g_wfrag (fp16 m16n8k16 fragments)
#define U_W1 0          // 128
#define U_W2 128        // 512
#define U_W3 640        // 512
#define U_W4 1152       // + chunk*512 (3 chunks)
#define U_WD 2688       // + l*512 (3 l's)

__device__ __forceinline__ float silu_f(float x) {
    return __fdividef(x, 1.f + __expf(-x));
}

// pack two f32 -> f16x2 {lo, hi}
__device__ __forceinline__ uint32_t f22h2(float lo, float hi) {
    uint32_t r;
    asm("cvt.rn.f16x2.f32 %0, %1, %2;" : "=r"(r) : "f"(hi), "f"(lo));
    return r;
}

__device__ __forceinline__ void mma_f16(float acc[4], uint32_t a0, uint32_t a1,
                                        uint32_t a2, uint32_t a3,
                                        uint32_t b0, uint32_t b1) {
    asm volatile(
        "mma.sync.aligned.m16n8k16.row.col.f32.f16.f16.f32 "
        "{%0,%1,%2,%3}, {%4,%5,%6,%7}, {%8,%9}, {%0,%1,%2,%3};\n"
        : "+f"(acc[0]), "+f"(acc[1]), "+f"(acc[2]), "+f"(acc[3])
        : "r"(a0), "r"(a1), "r"(a2), "r"(a3), "r"(b0), "r"(b1));
}

// fire-and-forget vector float2 reduction (sm_90+)
__device__ __forceinline__ void red2(float* p, float x, float y) {
    asm volatile("red.global.add.v2.f32 [%0], {%1, %2};"
                 :: "l"(p), "f"(x), "f"(y) : "memory");
}

// ---------------- launch 1: edge count histogram ONLY ----------------
__global__ __launch_bounds__(256) void k_hist(const int* __restrict__ recv) {
    int e = blockIdx.x * 256 + threadIdx.x;
    atomicAdd(&g_count[recv[e]], 1);          // N_EDGES % 256 == 0
}

// ---------------- launch 2: parallel exclusive scan (+ zero g_count) ----------------
__global__ __launch_bounds__(1024) void k_scan() {
    __shared__ int warpsum[32];
    int t = threadIdx.x, lane = t & 31, w = t >> 5;
    int base = t * 10;
    int c[10];
    int s = 0;
#pragma unroll
    for (int i = 0; i < 10; ++i) {
        int idx = base + i;
        c[i] = (idx < N_NODES) ? g_count[idx] : 0;
        s += c[i];
    }
    int pre = s;
#pragma unroll
    for (int d = 1; d < 32; d <<= 1) {
        int v = __shfl_up_sync(0xffffffffu, pre, d);
        if (lane >= d) pre += v;
    }
    if (lane == 31) warpsum[w] = pre;
    __syncthreads();
    if (w == 0) {
        int v = warpsum[lane];
#pragma unroll
        for (int d = 1; d < 32; d <<= 1) {
            int u = __shfl_up_sync(0xffffffffu, v, d);
            if (lane >= d) v += u;
        }
        warpsum[lane] = v;
    }
    __syncthreads();
    int wbase = (w > 0) ? warpsum[w - 1] : 0;
    int run = wbase + pre - s;
#pragma unroll
    for (int i = 0; i < 10; ++i) {
        int idx = base + i;
        if (idx < N_NODES) {
            g_rowstart[idx] = run;
            g_cursor[idx] = run;
            run += c[i];
            g_count[idx] = 0;
        }
    }
    if (t == 1023) g_rowstart[N_NODES] = warpsum[31];
}

// ---------------- launch 3: CSR fill (1250) || h GEMM + agg zero (1250) || weight prep (17) ----------------
__global__ __launch_bounds__(256) void k_fill_plus(const int* __restrict__ recv,
                                                   const int* __restrict__ send,
                                                   const float* __restrict__ nf,
                                                   const float* __restrict__ Wup,
                                                   const float* __restrict__ W1,
                                                   const float* __restrict__ W2,
                                                   const float* __restrict__ W3,
                                                   const float* __restrict__ W4,
                                                   const float* __restrict__ Wd) {
    int t = threadIdx.x;
    int b = blockIdx.x;

    if (b < 1250) {
        // CSR fill
        int e = b * 256 + t;
        int r = recv[e];
        int pos = atomicAdd(&g_cursor[r], 1);
        g_csr[pos] = e;
        g_send[pos] = send[e];
        g_recv[pos] = r;
        return;
    }

    if (b >= 2500) {
        // fp16 weight prep: uint4 = { b0(n0), b1(n0), b0(n1), b1(n1) }
        int u = (b - 2500) * 256 + t;
        if (u >= 4224) return;
        const float* src; int rs, co, KK, kmax, local;
        if (u < 128)        { src = W1; rs = 64;  co = 0;   KK = 1; kmax = 8;  local = u; }
        else if (u < 640)   { src = W2; rs = 64;  co = 0;   KK = 4; kmax = 64; local = u - 128; }
        else if (u < 1152)  { src = W3; rs = 64;  co = 0;   KK = 4; kmax = 64; local = u - 640; }
        else if (u < 1664)  { src = W4; rs = 192; co = 0;   KK = 4; kmax = 64; local = u - 1152; }
        else if (u < 2176)  { src = W4; rs = 192; co = 64;  KK = 4; kmax = 64; local = u - 1664; }
        else if (u < 2688)  { src = W4; rs = 192; co = 128; KK = 4; kmax = 64; local = u - 2176; }
        else { int v = u - 2688; src = Wd + (v / 512) * 4096;
               rs = 64; co = 0; KK = 4; kmax = 64; local = v & 511; }
        int lane = local & 31, rest = local >> 5;
        int kk = rest % KK, jp = rest / KK;
        int gid = lane >> 2, tid4 = lane & 3;
        int n0 = co + jp * 16 + gid, n1 = n0 + 8;
        int k0 = kk * 16 + 2 * tid4;
        uint32_t x = f22h2(src[(size_t)k0 * rs + n0], src[(size_t)(k0 + 1) * rs + n0]);
        uint32_t z = f22h2(src[(size_t)k0 * rs + n1], src[(size_t)(k0 + 1) * rs + n1]);
        uint32_t y = 0, w = 0;
        if (k0 + 8 < kmax) {
            y = f22h2(src[(size_t)(k0 + 8) * rs + n0], src[(size_t)(k0 + 9) * rs + n0]);
            w = f22h2(src[(size_t)(k0 + 8) * rs + n1], src[(size_t)(k0 + 9) * rs + n1]);
        }
        g_wfrag[u] = make_uint4(x, y, z, w);
        return;
    }

    // h GEMM block (nodes [hb*8, hb*8+8)) + zero its g_agg slice
    int hb = b - 1250;
    {
        float4* aggb = (float4*)g_agg + (size_t)hb * 1152;
        for (int i = t; i < 1152; i += 256)
            aggb[i] = make_float4(0.f, 0.f, 0.f, 0.f);
    }
    __shared__ float sW[64 * 64];
    __shared__ float sN[8 * 64];
    for (int idx = t; idx < 1024; idx += 256)
        ((float4*)sW)[idx] = ((const float4*)Wup)[idx];
    int n0 = hb * 8;                          // 1250 * 8 = 10000
    if (t < 128)
        ((float4*)sN)[t] = ((const float4*)(nf + (size_t)n0 * 64))[t];
    __syncthreads();

#pragma unroll
    for (int j = 0; j < 2; ++j) {
        int o = t + j * 256;
        int row = o >> 6, c = o & 63;
        float a0 = 0.f, a1 = 0.f;
#pragma unroll
        for (int k = 0; k < 64; k += 2) {
            a0 = fmaf(sN[row * 64 + k],     sW[k * 64 + c],       a0);
            a1 = fmaf(sN[row * 64 + k + 1], sW[(k + 1) * 64 + c], a1);
        }
        g_h[(size_t)(n0 + row) * 64 + c] = (a0 + a1) * 0.125f;
    }
}

// ---------------- launch 4 (profiled): warp-autonomous fused MLP + SH + TP + scatter ----------------
// fp16 m16n8k16 datapath; msg staged WITHOUT h (raw acc*S); h applied in the
// epilogue via coalesced per-row float2 loads (all lanes hit one g_h row).

template <int KK>
__device__ __forceinline__ void layer_f16(int base, const uint32_t A0[4],
                                          const uint32_t A1[4], const uint32_t A2[4],
                                          const uint32_t A3[4], float acc[8][4],
                                          int lane) {
#pragma unroll
    for (int j = 0; j < 8; ++j) {
        acc[j][0] = 0.f; acc[j][1] = 0.f; acc[j][2] = 0.f; acc[j][3] = 0.f;
    }
#pragma unroll
    for (int kk = 0; kk < KK; ++kk) {
#pragma unroll
        for (int jp = 0; jp < 4; ++jp) {
            uint4 b = __ldg(&g_wfrag[base + ((jp * KK + kk) * 32) + lane]);
            mma_f16(acc[2 * jp],     A0[kk], A1[kk], A2[kk], A3[kk], b.x, b.y);
            mma_f16(acc[2 * jp + 1], A0[kk], A1[kk], A2[kk], A3[kk], b.z, b.w);
        }
    }
}

// C-frags -> next layer A-frags: scale + silu + f16 pack, all lane-local.
__device__ __forceinline__ void cvt_f16(const float acc[8][4], float scale,
                                        uint32_t A0[4], uint32_t A1[4],
                                        uint32_t A2[4], uint32_t A3[4]) {
#pragma unroll
    for (int kk = 0; kk < 4; ++kk) {
        A0[kk] = f22h2(silu_f(acc[2 * kk][0] * scale),     silu_f(acc[2 * kk][1] * scale));
        A1[kk] = f22h2(silu_f(acc[2 * kk][2] * scale),     silu_f(acc[2 * kk][3] * scale));
        A2[kk] = f22h2(silu_f(acc[2 * kk + 1][0] * scale), silu_f(acc[2 * kk + 1][1] * scale));
        A3[kk] = f22h2(silu_f(acc[2 * kk + 1][2] * scale), silu_f(acc[2 * kk + 1][3] * scale));
    }
}

template <int D, int KOFF>
__device__ __forceinline__ void l4_chunk(int base, const uint32_t A0[4],
                                         const uint32_t A1[4], const uint32_t A2[4],
                                         const uint32_t A3[4],
                                         float* __restrict__ wMsg,
                                         const float* __restrict__ wSh,
                                         const int* __restrict__ wRecv,
                                         const int* __restrict__ wSend,
                                         int lane, int gid, int tid4) {
    float acc[8][4];
    layer_f16<4>(base, A0, A1, A2, A3, acc, lane);

    const float S = 1.f / 256.f;   // 1/sqrt(64) / avg_neigh
#pragma unroll
    for (int j = 0; j < 8; ++j) {
        int col = j * 8 + 2 * tid4;
        *(float2*)(wMsg + gid * 66 + col) =
            make_float2(acc[j][0] * S, acc[j][1] * S);
        *(float2*)(wMsg + (gid + 8) * 66 + col) =
            make_float2(acc[j][2] * S, acc[j][3] * S);
    }
    __syncwarp();

    // warp-local segment reduction: lane owns channels (2*lane, 2*lane+1);
    // h applied here with coalesced row loads.
    {
        int ncur = wRecv[0];
        float a[D][2];
#pragma unroll
        for (int k = 0; k < D; ++k) { a[k][0] = 0.f; a[k][1] = 0.f; }
#pragma unroll 4
        for (int r = 0; r < 16; ++r) {
            int n = wRecv[r];
            if (n != ncur) {
#pragma unroll
                for (int k = 0; k < D; ++k) {
                    red2(&g_agg[(size_t)(ncur * 9 + KOFF + k) * 64 + 2 * lane],
                         a[k][0], a[k][1]);
                    a[k][0] = 0.f; a[k][1] = 0.f;
                }
                ncur = n;
            }
            float2 m = *(const float2*)(wMsg + r * 66 + 2 * lane);
            float2 h2 = *(const float2*)(g_h + (size_t)wSend[r] * 64 + 2 * lane);
            float mx = m.x * h2.x, my = m.y * h2.y;
#pragma unroll
            for (int k = 0; k < D; ++k) {
                float s = wSh[r * 12 + KOFF + k];
                a[k][0] = fmaf(mx, s, a[k][0]);
                a[k][1] = fmaf(my, s, a[k][1]);
            }
        }
#pragma unroll
        for (int k = 0; k < D; ++k)
            red2(&g_agg[(size_t)(ncur * 9 + KOFF + k) * 64 + 2 * lane],
                 a[k][0], a[k][1]);
    }
    __syncwarp();
}

__global__ __launch_bounds__(256, 2) void k_edge(const float* __restrict__ evec,
                                                 const float* __restrict__ rad) {
    __shared__ __align__(16) float sMsgAll[8][16 * 66];   // 33792 B
    __shared__ __align__(16) float sShAll[8][16 * 12];    // 6144 B
    __shared__ int sMeta[8][32];                          // 1024 B

    int t = threadIdx.x, lane = t & 31, warp = t >> 5;
    int gid = lane >> 2, tid4 = lane & 3;
    float* wMsg = sMsgAll[warp];
    float* wSh  = sShAll[warp];
    int* wRecv  = sMeta[warp];
    int* wSend  = sMeta[warp] + 16;
    int pos0 = blockIdx.x * 128 + warp * 16;

    // init: lanes 0..15 handle one row each (SH + meta)
    if (lane < 16) {
        int pos = pos0 + lane;
        int e = g_csr[pos];
        wRecv[lane] = g_recv[pos];
        wSend[lane] = g_send[pos];
        float x = evec[(size_t)e * 3], y = evec[(size_t)e * 3 + 1],
              z = evec[(size_t)e * 3 + 2];
        float rn = rsqrtf(x * x + y * y + z * z);
        x *= rn; y *= rn; z *= rn;
        const float c3  = 1.7320508075688772f;
        const float c15 = 3.872983346207417f;
        const float c5h = 1.118033988749895f;
        const float c15h= 1.9364916731037085f;
        float* o = wSh + lane * 12;
        o[0] = 1.f;
        o[1] = c3 * x; o[2] = c3 * y; o[3] = c3 * z;
        o[4] = c15 * x * y; o[5] = c15 * y * z;
        o[6] = c5h * (3.f * z * z - 1.f);
        o[7] = c15 * x * z; o[8] = c15h * (x * x - y * y);
    }
    __syncwarp();

    // L1 A-fragments straight from rad (rows gid, gid+8; k-cols 2*tid4, +1; high-k = 0)
    int e0 = g_csr[pos0 + gid], e1 = g_csr[pos0 + gid + 8];
    float2 ra0 = *(const float2*)(rad + (size_t)e0 * 8 + 2 * tid4);
    float2 ra1 = *(const float2*)(rad + (size_t)e1 * 8 + 2 * tid4);

    float acc[8][4];
    uint32_t A0[4], A1[4], A2[4], A3[4];
    A0[0] = f22h2(ra0.x, ra0.y);
    A1[0] = f22h2(ra1.x, ra1.y);
    A2[0] = 0u;
    A3[0] = 0u;

    // L1: [16,8]@[8,64]
    layer_f16<1>(U_W1, A0, A1, A2, A3, acc, lane);
    cvt_f16(acc, 0.35355339059327373f, A0, A1, A2, A3);

    // L2
    layer_f16<4>(U_W2, A0, A1, A2, A3, acc, lane);
    cvt_f16(acc, 0.125f, A0, A1, A2, A3);

    // L3
    layer_f16<4>(U_W3, A0, A1, A2, A3, acc, lane);
    cvt_f16(acc, 0.125f, A0, A1, A2, A3);

    // L4 chunks + tensor product + warp-local segment scatter
    l4_chunk<1, 0>(U_W4 + 0 * 512, A0, A1, A2, A3,
                   wMsg, wSh, wRecv, wSend, lane, gid, tid4);
    l4_chunk<3, 1>(U_W4 + 1 * 512, A0, A1, A2, A3,
                   wMsg, wSh, wRecv, wSend, lane, gid, tid4);
    l4_chunk<5, 4>(U_W4 + 2 * 512, A0, A1, A2, A3,
                   wMsg, wSh, wRecv, wSend, lane, gid, tid4);
}

// ---------------- launch 5: linear_down as warp-autonomous fp16 MMA ----------------
template <int D, int KOFF, int OFF>
__device__ __forceinline__ void down_tile(int tile, int wbase, float* __restrict__ out,
                                          int lane, int gid, int tid4) {
    int R0 = tile * 16 + gid, R1 = R0 + 8;
    int n0, m0, n1, m1;
    if (D == 1) { n0 = R0; m0 = 0; n1 = R1; m1 = 0; }
    else {
        n0 = R0 / D; m0 = R0 - n0 * D;
        n1 = R1 / D; m1 = R1 - n1 * D;
    }
    const float* p0 = g_agg + (size_t)n0 * 576 + (KOFF + m0) * 64;
    const float* p1 = g_agg + (size_t)n1 * 576 + (KOFF + m1) * 64;

    float acc[8][4];
#pragma unroll
    for (int j = 0; j < 8; ++j) {
        acc[j][0] = 0.f; acc[j][1] = 0.f; acc[j][2] = 0.f; acc[j][3] = 0.f;
    }
#pragma unroll
    for (int kk = 0; kk < 4; ++kk) {
        int c0 = kk * 16 + 2 * tid4;
        float2 v00 = *(const float2*)(p0 + c0);
        float2 v01 = *(const float2*)(p0 + c0 + 8);
        float2 v10 = *(const float2*)(p1 + c0);
        float2 v11 = *(const float2*)(p1 + c0 + 8);
        uint32_t a0 = f22h2(v00.x, v00.y);
        uint32_t a1 = f22h2(v10.x, v10.y);
        uint32_t a2 = f22h2(v01.x, v01.y);
        uint32_t a3 = f22h2(v11.x, v11.y);
#pragma unroll
        for (int jp = 0; jp < 4; ++jp) {
            uint4 b = __ldg(&g_wfrag[wbase + ((jp * 4 + kk) * 32) + lane]);
            mma_f16(acc[2 * jp],     a0, a1, a2, a3, b.x, b.y);
            mma_f16(acc[2 * jp + 1], a0, a1, a2, a3, b.z, b.w);
        }
    }

    float* o0 = out + (size_t)n0 * 576 + OFF + m0;
    float* o1 = out + (size_t)n1 * 576 + OFF + m1;
#pragma unroll
    for (int j = 0; j < 8; ++j) {
        int dch = j * 8 + 2 * tid4;
        o0[dch * D]       = acc[j][0] * 0.125f;
        o0[(dch + 1) * D] = acc[j][1] * 0.125f;
        o1[dch * D]       = acc[j][2] * 0.125f;
        o1[(dch + 1) * D] = acc[j][3] * 0.125f;
    }
}

__global__ __launch_bounds__(256) void k_down(float* __restrict__ out) {
    int t = threadIdx.x, lane = t & 31, warp = t >> 5;
    int gid = lane >> 2, tid4 = lane & 3;
    int W = blockIdx.x * 8 + warp;
    if (W < 625)
        down_tile<1, 0, 0>(W, U_WD, out, lane, gid, tid4);
    else if (W < 2500)
        down_tile<3, 1, 64>(W - 625, U_WD + 512, out, lane, gid, tid4);
    else if (W < 5625)
        down_tile<5, 4, 256>(W - 2500, U_WD + 1024, out, lane, gid, tid4);
}

// ---------------- launch ----------------
extern "C" void kernel_launch(void* const* d_in, const int* in_sizes, int n_in,
                              void* d_out, int out_size) {
    const float* evec = (const float*)d_in[0];
    const float* nf   = (const float*)d_in[1];
    const float* rad  = (const float*)d_in[2];
    const int* senders   = (const int*)d_in[3];
    const int* receivers = (const int*)d_in[4];
    const float* Wup = (const float*)d_in[5];
    const float* W1  = (const float*)d_in[6];
    const float* W2  = (const float*)d_in[7];
    const float* W3  = (const float*)d_in[8];
    const float* W4  = (const float*)d_in[9];
    const float* Wd  = (const float*)d_in[10];
    float* out = (float*)d_out;

    k_hist<<<N_EDGES / 256, 256>>>(receivers);
    k_scan<<<1, 1024>>>();
    k_fill_plus<<<2517, 256>>>(receivers, senders, nf, Wup, W1, W2, W3, W4, Wd);
    k_edge<<<N_EDGES / 128, 256>>>(evec, rad);
    k_down<<<704, 256>>>(out);
}

// round 17
// speedup vs baseline: 1.2029x; 1.2029x over previous
#include <cuda_runtime.h>
#include <cstdint>

#define N_NODES 10000
#define N_EDGES 320000

// ---------------- scratch (device globals; allocation-free) ----------------
__device__ float g_h[N_NODES * 64];                 // 2.56 MB
__device__ float g_agg[(size_t)N_NODES * 576];      // 23 MB; zeroed by k_fill_plus each call
__device__ int   g_count[N_NODES];                  // zeroed by k_scan after read
__device__ int   g_rowstart[N_NODES + 1];
__device__ int   g_cursor[N_NODES];
__device__ int   g_csr[N_EDGES];
__device__ int   g_send[N_EDGES];
__device__ int   g_recv[N_EDGES];
__device__ uint4 g_wfrag[4224];                     // fragment-ordered fp16 weights (67.6KB)

// uint4 offsets into g_wfrag (fp16 m16n8k16 fragments)
#define U_W1 0          // 128
#define U_W2 128        // 512
#define U_W3 640        // 512
#define U_W4 1152       // + chunk*512 (3 chunks)
#define U_WD 2688       // + l*512 (3 l's)

__device__ __forceinline__ float silu_f(float x) {
    return __fdividef(x, 1.f + __expf(-x));
}

// pack two f32 -> f16x2 {lo, hi}
__device__ __forceinline__ uint32_t f22h2(float lo, float hi) {
    uint32_t r;
    asm("cvt.rn.f16x2.f32 %0, %1, %2;" : "=r"(r) : "f"(hi), "f"(lo));
    return r;
}

__device__ __forceinline__ void mma_f16(float acc[4], uint32_t a0, uint32_t a1,
                                        uint32_t a2, uint32_t a3,
                                        uint32_t b0, uint32_t b1) {
    asm volatile(
        "mma.sync.aligned.m16n8k16.row.col.f32.f16.f16.f32 "
        "{%0,%1,%2,%3}, {%4,%5,%6,%7}, {%8,%9}, {%0,%1,%2,%3};\n"
        : "+f"(acc[0]), "+f"(acc[1]), "+f"(acc[2]), "+f"(acc[3])
        : "r"(a0), "r"(a1), "r"(a2), "r"(a3), "r"(b0), "r"(b1));
}

// fire-and-forget vector float2 reduction (sm_90+)
__device__ __forceinline__ void red2(float* p, float x, float y) {
    asm volatile("red.global.add.v2.f32 [%0], {%1, %2};"
                 :: "l"(p), "f"(x), "f"(y) : "memory");
}

// ---------------- launch 1: edge count histogram ONLY ----------------
__global__ __launch_bounds__(256) void k_hist(const int* __restrict__ recv) {
    int e = blockIdx.x * 256 + threadIdx.x;
    atomicAdd(&g_count[recv[e]], 1);          // N_EDGES % 256 == 0
}

// ---------------- launch 2: parallel exclusive scan (+ zero g_count) ----------------
__global__ __launch_bounds__(1024) void k_scan() {
    __shared__ int warpsum[32];
    int t = threadIdx.x, lane = t & 31, w = t >> 5;
    int base = t * 10;
    int c[10];
    int s = 0;
#pragma unroll
    for (int i = 0; i < 10; ++i) {
        int idx = base + i;
        c[i] = (idx < N_NODES) ? g_count[idx] : 0;
        s += c[i];
    }
    int pre = s;
#pragma unroll
    for (int d = 1; d < 32; d <<= 1) {
        int v = __shfl_up_sync(0xffffffffu, pre, d);
        if (lane >= d) pre += v;
    }
    if (lane == 31) warpsum[w] = pre;
    __syncthreads();
    if (w == 0) {
        int v = warpsum[lane];
#pragma unroll
        for (int d = 1; d < 32; d <<= 1) {
            int u = __shfl_up_sync(0xffffffffu, v, d);
            if (lane >= d) v += u;
        }
        warpsum[lane] = v;
    }
    __syncthreads();
    int wbase = (w > 0) ? warpsum[w - 1] : 0;
    int run = wbase + pre - s;
#pragma unroll
    for (int i = 0; i < 10; ++i) {
        int idx = base + i;
        if (idx < N_NODES) {
            g_rowstart[idx] = run;
            g_cursor[idx] = run;
            run += c[i];
            g_count[idx] = 0;
        }
    }
    if (t == 1023) g_rowstart[N_NODES] = warpsum[31];
}

// ---------------- launch 3: CSR fill (1250) || h GEMM + agg zero (1250) || weight prep (17) ----------------
__global__ __launch_bounds__(256) void k_fill_plus(const int* __restrict__ recv,
                                                   const int* __restrict__ send,
                                                   const float* __restrict__ nf,
                                                   const float* __restrict__ Wup,
                                                   const float* __restrict__ W1,
                                                   const float* __restrict__ W2,
                                                   const float* __restrict__ W3,
                                                   const float* __restrict__ W4,
                                                   const float* __restrict__ Wd) {
    int t = threadIdx.x;
    int b = blockIdx.x;

    if (b < 1250) {
        // CSR fill
        int e = b * 256 + t;
        int r = recv[e];
        int pos = atomicAdd(&g_cursor[r], 1);
        g_csr[pos] = e;
        g_send[pos] = send[e];
        g_recv[pos] = r;
        return;
    }

    if (b >= 2500) {
        // fp16 weight prep: uint4 = { b0(n0), b1(n0), b0(n1), b1(n1) }
        int u = (b - 2500) * 256 + t;
        if (u >= 4224) return;
        const float* src; int rs, co, KK, kmax, local;
        if (u < 128)        { src = W1; rs = 64;  co = 0;   KK = 1; kmax = 8;  local = u; }
        else if (u < 640)   { src = W2; rs = 64;  co = 0;   KK = 4; kmax = 64; local = u - 128; }
        else if (u < 1152)  { src = W3; rs = 64;  co = 0;   KK = 4; kmax = 64; local = u - 640; }
        else if (u < 1664)  { src = W4; rs = 192; co = 0;   KK = 4; kmax = 64; local = u - 1152; }
        else if (u < 2176)  { src = W4; rs = 192; co = 64;  KK = 4; kmax = 64; local = u - 1664; }
        else if (u < 2688)  { src = W4; rs = 192; co = 128; KK = 4; kmax = 64; local = u - 2176; }
        else { int v = u - 2688; src = Wd + (v / 512) * 4096;
               rs = 64; co = 0; KK = 4; kmax = 64; local = v & 511; }
        int lane = local & 31, rest = local >> 5;
        int kk = rest % KK, jp = rest / KK;
        int gid = lane >> 2, tid4 = lane & 3;
        int n0 = co + jp * 16 + gid, n1 = n0 + 8;
        int k0 = kk * 16 + 2 * tid4;
        uint32_t x = f22h2(src[(size_t)k0 * rs + n0], src[(size_t)(k0 + 1) * rs + n0]);
        uint32_t z = f22h2(src[(size_t)k0 * rs + n1], src[(size_t)(k0 + 1) * rs + n1]);
        uint32_t y = 0, w = 0;
        if (k0 + 8 < kmax) {
            y = f22h2(src[(size_t)(k0 + 8) * rs + n0], src[(size_t)(k0 + 9) * rs + n0]);
            w = f22h2(src[(size_t)(k0 + 8) * rs + n1], src[(size_t)(k0 + 9) * rs + n1]);
        }
        g_wfrag[u] = make_uint4(x, y, z, w);
        return;
    }

    // h GEMM block (nodes [hb*8, hb*8+8)) + zero its g_agg slice
    int hb = b - 1250;
    {
        float4* aggb = (float4*)g_agg + (size_t)hb * 1152;
        for (int i = t; i < 1152; i += 256)
            aggb[i] = make_float4(0.f, 0.f, 0.f, 0.f);
    }
    __shared__ float sW[64 * 64];
    __shared__ float sN[8 * 64];
    for (int idx = t; idx < 1024; idx += 256)
        ((float4*)sW)[idx] = ((const float4*)Wup)[idx];
    int n0 = hb * 8;                          // 1250 * 8 = 10000
    if (t < 128)
        ((float4*)sN)[t] = ((const float4*)(nf + (size_t)n0 * 64))[t];
    __syncthreads();

#pragma unroll
    for (int j = 0; j < 2; ++j) {
        int o = t + j * 256;
        int row = o >> 6, c = o & 63;
        float a0 = 0.f, a1 = 0.f;
#pragma unroll
        for (int k = 0; k < 64; k += 2) {
            a0 = fmaf(sN[row * 64 + k],     sW[k * 64 + c],       a0);
            a1 = fmaf(sN[row * 64 + k + 1], sW[(k + 1) * 64 + c], a1);
        }
        g_h[(size_t)(n0 + row) * 64 + c] = (a0 + a1) * 0.125f;
    }
}

// ---------------- launch 4 (profiled): warp-autonomous fused MLP + SH + TP + scatter ----------------
// fp16 m16n8k16 datapath; h register-resident across chunks (R14 champion
// structure); sh stored with pitch 16 for vectorized broadcast reads.

template <int KK>
__device__ __forceinline__ void layer_f16(int base, const uint32_t A0[4],
                                          const uint32_t A1[4], const uint32_t A2[4],
                                          const uint32_t A3[4], float acc[8][4],
                                          int lane) {
#pragma unroll
    for (int j = 0; j < 8; ++j) {
        acc[j][0] = 0.f; acc[j][1] = 0.f; acc[j][2] = 0.f; acc[j][3] = 0.f;
    }
#pragma unroll
    for (int kk = 0; kk < KK; ++kk) {
#pragma unroll
        for (int jp = 0; jp < 4; ++jp) {
            uint4 b = __ldg(&g_wfrag[base + ((jp * KK + kk) * 32) + lane]);
            mma_f16(acc[2 * jp],     A0[kk], A1[kk], A2[kk], A3[kk], b.x, b.y);
            mma_f16(acc[2 * jp + 1], A0[kk], A1[kk], A2[kk], A3[kk], b.z, b.w);
        }
    }
}

// C-frags -> next layer A-frags: scale + silu + f16 pack, all lane-local.
__device__ __forceinline__ void cvt_f16(const float acc[8][4], float scale,
                                        uint32_t A0[4], uint32_t A1[4],
                                        uint32_t A2[4], uint32_t A3[4]) {
#pragma unroll
    for (int kk = 0; kk < 4; ++kk) {
        A0[kk] = f22h2(silu_f(acc[2 * kk][0] * scale),     silu_f(acc[2 * kk][1] * scale));
        A1[kk] = f22h2(silu_f(acc[2 * kk][2] * scale),     silu_f(acc[2 * kk][3] * scale));
        A2[kk] = f22h2(silu_f(acc[2 * kk + 1][0] * scale), silu_f(acc[2 * kk + 1][1] * scale));
        A3[kk] = f22h2(silu_f(acc[2 * kk + 1][2] * scale), silu_f(acc[2 * kk + 1][3] * scale));
    }
}

template <int D, int KOFF>
__device__ __forceinline__ void l4_chunk(int base, const uint32_t A0[4],
                                         const uint32_t A1[4], const uint32_t A2[4],
                                         const uint32_t A3[4],
                                         const float2 hf0[8], const float2 hf1[8],
                                         float* __restrict__ wMsg,
                                         const float* __restrict__ wSh,
                                         const int* __restrict__ wRecv,
                                         int lane, int gid, int tid4) {
    float acc[8][4];
    layer_f16<4>(base, A0, A1, A2, A3, acc, lane);

    const float S = 1.f / 256.f;   // 1/sqrt(64) / avg_neigh
#pragma unroll
    for (int j = 0; j < 8; ++j) {
        int col = j * 8 + 2 * tid4;
        *(float2*)(wMsg + gid * 66 + col) =
            make_float2(acc[j][0] * hf0[j].x * S, acc[j][1] * hf0[j].y * S);
        *(float2*)(wMsg + (gid + 8) * 66 + col) =
            make_float2(acc[j][2] * hf1[j].x * S, acc[j][3] * hf1[j].y * S);
    }
    __syncwarp();

    // warp-local segment reduction: lane owns channels (2*lane, 2*lane+1);
    // sh loaded with vectorized broadcast reads (pitch 16).
    {
        int ncur = wRecv[0];
        float a[D][2];
#pragma unroll
        for (int k = 0; k < D; ++k) { a[k][0] = 0.f; a[k][1] = 0.f; }
#pragma unroll 4
        for (int r = 0; r < 16; ++r) {
            int n = wRecv[r];
            if (n != ncur) {
#pragma unroll
                for (int k = 0; k < D; ++k) {
                    red2(&g_agg[(size_t)(ncur * 9 + KOFF + k) * 64 + 2 * lane],
                         a[k][0], a[k][1]);
                    a[k][0] = 0.f; a[k][1] = 0.f;
                }
                ncur = n;
            }
            float2 m = *(const float2*)(wMsg + r * 66 + 2 * lane);
            float s[D];
            if (D == 1) {
                s[0] = wSh[r * 16];
            } else if (D == 3) {
                float4 v = *(const float4*)(wSh + r * 16);
                s[0] = v.y; s[1] = v.z; s[2] = v.w;
            } else {
                float4 v = *(const float4*)(wSh + r * 16 + 4);
                s[0] = v.x; s[1] = v.y; s[2] = v.z; s[3] = v.w;
                s[4] = wSh[r * 16 + 8];
            }
#pragma unroll
            for (int k = 0; k < D; ++k) {
                a[k][0] = fmaf(m.x, s[k], a[k][0]);
                a[k][1] = fmaf(m.y, s[k], a[k][1]);
            }
        }
#pragma unroll
        for (int k = 0; k < D; ++k)
            red2(&g_agg[(size_t)(ncur * 9 + KOFF + k) * 64 + 2 * lane],
                 a[k][0], a[k][1]);
    }
    __syncwarp();
}

__global__ __launch_bounds__(256, 2) void k_edge(const float* __restrict__ evec,
                                                 const float* __restrict__ rad) {
    __shared__ __align__(16) float sMsgAll[8][16 * 66];   // 33792 B
    __shared__ __align__(16) float sShAll[8][16 * 16];    // 8192 B
    __shared__ int sMeta[8][32];                          // 1024 B

    int t = threadIdx.x, lane = t & 31, warp = t >> 5;
    int gid = lane >> 2, tid4 = lane & 3;
    float* wMsg = sMsgAll[warp];
    float* wSh  = sShAll[warp];
    int* wRecv  = sMeta[warp];
    int* wSend  = sMeta[warp] + 16;
    int pos0 = blockIdx.x * 128 + warp * 16;

    // init: lanes 0..15 handle one row each (SH + meta)
    if (lane < 16) {
        int pos = pos0 + lane;
        int e = g_csr[pos];
        wRecv[lane] = g_recv[pos];
        wSend[lane] = g_send[pos];
        float x = evec[(size_t)e * 3], y = evec[(size_t)e * 3 + 1],
              z = evec[(size_t)e * 3 + 2];
        float rn = rsqrtf(x * x + y * y + z * z);
        x *= rn; y *= rn; z *= rn;
        const float c3  = 1.7320508075688772f;
        const float c15 = 3.872983346207417f;
        const float c5h = 1.118033988749895f;
        const float c15h= 1.9364916731037085f;
        float* o = wSh + lane * 16;
        o[0] = 1.f;
        o[1] = c3 * x; o[2] = c3 * y; o[3] = c3 * z;
        o[4] = c15 * x * y; o[5] = c15 * y * z;
        o[6] = c5h * (3.f * z * z - 1.f);
        o[7] = c15 * x * z; o[8] = c15h * (x * x - y * y);
    }
    __syncwarp();

    // L1 A-fragments straight from rad (rows gid, gid+8; k-cols 2*tid4, +1; high-k = 0)
    int e0 = g_csr[pos0 + gid], e1 = g_csr[pos0 + gid + 8];
    float2 ra0 = *(const float2*)(rad + (size_t)e0 * 8 + 2 * tid4);
    float2 ra1 = *(const float2*)(rad + (size_t)e1 * 8 + 2 * tid4);

    float acc[8][4];
    uint32_t A0[4], A1[4], A2[4], A3[4];
    A0[0] = f22h2(ra0.x, ra0.y);
    A1[0] = f22h2(ra1.x, ra1.y);
    A2[0] = 0u;
    A3[0] = 0u;

    // L1: [16,8]@[8,64]
    layer_f16<1>(U_W1, A0, A1, A2, A3, acc, lane);
    cvt_f16(acc, 0.35355339059327373f, A0, A1, A2, A3);

    // L2
    layer_f16<4>(U_W2, A0, A1, A2, A3, acc, lane);
    cvt_f16(acc, 0.125f, A0, A1, A2, A3);

    // L3
    layer_f16<4>(U_W3, A0, A1, A2, A3, acc, lane);
    cvt_f16(acc, 0.125f, A0, A1, A2, A3);

    // h fragments (register-resident across all 3 chunks)
    int s0r = wSend[gid], s1r = wSend[gid + 8];
    float2 hf0[8], hf1[8];
#pragma unroll
    for (int j = 0; j < 8; ++j) {
        hf0[j] = *(const float2*)(g_h + (size_t)s0r * 64 + j * 8 + 2 * tid4);
        hf1[j] = *(const float2*)(g_h + (size_t)s1r * 64 + j * 8 + 2 * tid4);
    }

    // L4 chunks + tensor product + warp-local segment scatter
    l4_chunk<1, 0>(U_W4 + 0 * 512, A0, A1, A2, A3, hf0, hf1,
                   wMsg, wSh, wRecv, lane, gid, tid4);
    l4_chunk<3, 1>(U_W4 + 1 * 512, A0, A1, A2, A3, hf0, hf1,
                   wMsg, wSh, wRecv, lane, gid, tid4);
    l4_chunk<5, 4>(U_W4 + 2 * 512, A0, A1, A2, A3, hf0, hf1,
                   wMsg, wSh, wRecv, lane, gid, tid4);
}

// ---------------- launch 5: linear_down as warp-autonomous fp16 MMA ----------------
template <int D, int KOFF, int OFF>
__device__ __forceinline__ void down_tile(int tile, int wbase, float* __restrict__ out,
                                          int lane, int gid, int tid4) {
    int R0 = tile * 16 + gid, R1 = R0 + 8;
    int n0, m0, n1, m1;
    if (D == 1) { n0 = R0; m0 = 0; n1 = R1; m1 = 0; }
    else {
        n0 = R0 / D; m0 = R0 - n0 * D;
        n1 = R1 / D; m1 = R1 - n1 * D;
    }
    const float* p0 = g_agg + (size_t)n0 * 576 + (KOFF + m0) * 64;
    const float* p1 = g_agg + (size_t)n1 * 576 + (KOFF + m1) * 64;

    float acc[8][4];
#pragma unroll
    for (int j = 0; j < 8; ++j) {
        acc[j][0] = 0.f; acc[j][1] = 0.f; acc[j][2] = 0.f; acc[j][3] = 0.f;
    }
#pragma unroll
    for (int kk = 0; kk < 4; ++kk) {
        int c0 = kk * 16 + 2 * tid4;
        float2 v00 = *(const float2*)(p0 + c0);
        float2 v01 = *(const float2*)(p0 + c0 + 8);
        float2 v10 = *(const float2*)(p1 + c0);
        float2 v11 = *(const float2*)(p1 + c0 + 8);
        uint32_t a0 = f22h2(v00.x, v00.y);
        uint32_t a1 = f22h2(v10.x, v10.y);
        uint32_t a2 = f22h2(v01.x, v01.y);
        uint32_t a3 = f22h2(v11.x, v11.y);
#pragma unroll
        for (int jp = 0; jp < 4; ++jp) {
            uint4 b = __ldg(&g_wfrag[wbase + ((jp * 4 + kk) * 32) + lane]);
            mma_f16(acc[2 * jp],     a0, a1, a2, a3, b.x, b.y);
            mma_f16(acc[2 * jp + 1], a0, a1, a2, a3, b.z, b.w);
        }
    }

    float* o0 = out + (size_t)n0 * 576 + OFF + m0;
    float* o1 = out + (size_t)n1 * 576 + OFF + m1;
#pragma unroll
    for (int j = 0; j < 8; ++j) {
        int dch = j * 8 + 2 * tid4;
        o0[dch * D]       = acc[j][0] * 0.125f;
        o0[(dch + 1) * D] = acc[j][1] * 0.125f;
        o1[dch * D]       = acc[j][2] * 0.125f;
        o1[(dch + 1) * D] = acc[j][3] * 0.125f;
    }
}

__global__ __launch_bounds__(256) void k_down(float* __restrict__ out) {
    int t = threadIdx.x, lane = t & 31, warp = t >> 5;
    int gid = lane >> 2, tid4 = lane & 3;
    int W = blockIdx.x * 8 + warp;
    if (W < 625)
        down_tile<1, 0, 0>(W, U_WD, out, lane, gid, tid4);
    else if (W < 2500)
        down_tile<3, 1, 64>(W - 625, U_WD + 512, out, lane, gid, tid4);
    else if (W < 5625)
        down_tile<5, 4, 256>(W - 2500, U_WD + 1024, out, lane, gid, tid4);
}

// ---------------- launch ----------------
extern "C" void kernel_launch(void* const* d_in, const int* in_sizes, int n_in,
                              void* d_out, int out_size) {
    const float* evec = (const float*)d_in[0];
    const float* nf   = (const float*)d_in[1];
    const float* rad  = (const float*)d_in[2];
    const int* senders   = (const int*)d_in[3];
    const int* receivers = (const int*)d_in[4];
    const float* Wup = (const float*)d_in[5];
    const float* W1  = (const float*)d_in[6];
    const float* W2  = (const float*)d_in[7];
    const float* W3  = (const float*)d_in[8];
    const float* W4  = (const float*)d_in[9];
    const float* Wd  = (const float*)d_in[10];
    float* out = (float*)d_out;

    k_hist<<<N_EDGES / 256, 256>>>(receivers);
    k_scan<<<1, 1024>>>();
    k_fill_plus<<<2517, 256>>>(receivers, senders, nf, Wup, W1, W2, W3, W4, Wd);
    k_edge<<<N_EDGES / 128, 256>>>(evec, rad);
    k_down<<<704, 256>>>(out);
}